// round 2
// baseline (speedup 1.0000x reference)
#include <cuda_runtime.h>
#include <math.h>

// Problem constants
#define SEQ  2048
#define BSZ  32
#define HD   256
#define IND  512
#define MROWS (SEQ*BSZ)        // 65536 rows for all big GEMMs
#define ELEMS (BSZ*HD)         // 8192 independent scan chains per direction
#define XXOFF ((size_t)BSZ*SEQ*2*HD)   // 33554432 : offset of h_out region in d_out

// Scratch (device globals; no allocation allowed). 4 x 64MB.
// buf0 = X0 (proj out, scan order), later reused as G1l
// buf1 = G0 (layer0 gates),        later reused as G1r
// buf2 = Y0l, buf3 = Y0r
__device__ float g_buf0[MROWS*HD];
__device__ float g_buf1[MROWS*HD];
__device__ float g_buf2[MROWS*HD];
__device__ float g_buf3[MROWS*HD];

// ---------------------------------------------------------------------------
// Fused SGEMM:  C[m,n] = act( sum_k A[m,k] * W[n,k] + bias[n] )
//   MODE 0 (proj): act = identity, output row remapped  m=b*SEQ+t -> row t*BSZ+b
//   MODE 1 (gate): act = sigmoid,  output row = m  (input already scan order)
// BM=128, BN=128, BK=16, TM=TN=8, 256 threads.
// All dims divide evenly (M=65536, N=256, K in {512,256}) -> no bounds checks.
// ---------------------------------------------------------------------------
#define BM 128
#define BN 128
#define BK 16
#define TM 8
#define TN 8

template<int MODE>
__global__ __launch_bounds__(256, 2)
void gemm_fused(const float* __restrict__ A, const float* __restrict__ W,
                const float* __restrict__ bias, float* __restrict__ out, int K)
{
    __shared__ float As[BK][BM];
    __shared__ float Ws[BK][BN];

    const int tid = threadIdx.x;        // 0..255
    const int m0  = blockIdx.y * BM;
    const int n0  = blockIdx.x * BN;
    const int tx  = tid & 15;           // 0..15
    const int ty  = tid >> 4;           // 0..15

    float acc[TM][TN];
    #pragma unroll
    for (int i = 0; i < TM; i++)
        #pragma unroll
        for (int j = 0; j < TN; j++) acc[i][j] = 0.f;

    for (int k0 = 0; k0 < K; k0 += BK) {
        // Load A tile (128x16) as float4, store transposed -> As[k][m]
        #pragma unroll
        for (int i = 0; i < 2; i++) {
            int f   = tid + i * 256;          // 0..511 float4 id
            int row = f >> 2;                 // 0..127
            int kf  = (f & 3) * 4;            // 0,4,8,12
            float4 v = *(const float4*)(A + (size_t)(m0 + row) * K + k0 + kf);
            As[kf + 0][row] = v.x; As[kf + 1][row] = v.y;
            As[kf + 2][row] = v.z; As[kf + 3][row] = v.w;
        }
        // Load W tile (128 n-rows x 16 k) -> Ws[k][n]
        #pragma unroll
        for (int i = 0; i < 2; i++) {
            int f   = tid + i * 256;
            int row = f >> 2;
            int kf  = (f & 3) * 4;
            float4 v = *(const float4*)(W + (size_t)(n0 + row) * K + k0 + kf);
            Ws[kf + 0][row] = v.x; Ws[kf + 1][row] = v.y;
            Ws[kf + 2][row] = v.z; Ws[kf + 3][row] = v.w;
        }
        __syncthreads();

        #pragma unroll
        for (int kk = 0; kk < BK; kk++) {
            float rm[TM], rn[TN];
            #pragma unroll
            for (int i = 0; i < TM; i++) rm[i] = As[kk][ty * TM + i];
            #pragma unroll
            for (int j = 0; j < TN; j++) rn[j] = Ws[kk][tx * TN + j];
            #pragma unroll
            for (int i = 0; i < TM; i++)
                #pragma unroll
                for (int j = 0; j < TN; j++)
                    acc[i][j] = fmaf(rm[i], rn[j], acc[i][j]);
        }
        __syncthreads();
    }

    // Epilogue
    #pragma unroll
    for (int i = 0; i < TM; i++) {
        int m = m0 + ty * TM + i;
        size_t orow;
        if (MODE == 0) {                 // proj: m = b*SEQ + t  ->  row t*BSZ + b
            int b = m >> 11;             // /SEQ
            int t = m & (SEQ - 1);
            orow = (size_t)(t * BSZ + b) * HD;
        } else {
            orow = (size_t)m * HD;
        }
        #pragma unroll
        for (int j = 0; j < TN; j++) {
            int n = n0 + tx * TN + j;
            float v = acc[i][j] + bias[n];
            if (MODE == 1) v = 1.0f / (1.0f + __expf(-v));
            out[orow + n] = v;
        }
    }
}

// ---------------------------------------------------------------------------
// Layer-0 scan. 64 blocks x 256 threads. blocks [0,32): ltr, [32,64): rtl.
// X,G in scan order [t][b][h]. rtl reads flipped. Writes Y in scan order.
// h_last -> d_out[XXOFF + slot*ELEMS + e], slots 0 (ltr) / 1 (rtl).
// ---------------------------------------------------------------------------
__global__ __launch_bounds__(256)
void scan_l0(const float* __restrict__ X, const float* __restrict__ G,
             float* __restrict__ Yl, float* __restrict__ Yr,
             float* __restrict__ dout)
{
    const int e   = (blockIdx.x & 31) * 256 + threadIdx.x;   // 0..8191
    const int dir = blockIdx.x >> 5;
    float h = 0.f;
    if (dir == 0) {
        #pragma unroll 2
        for (int t = 0; t < SEQ; t++) {
            size_t idx = (size_t)t * ELEMS + e;
            float x = X[idx], g = G[idx];
            float r = fmaf(g, h - x, x);       // g*h + (1-g)*x
            h = tanhf(x * r);
            Yl[idx] = h;
        }
        dout[XXOFF + 0 * ELEMS + e] = h;
    } else {
        #pragma unroll 2
        for (int t = 0; t < SEQ; t++) {
            size_t ridx = (size_t)(SEQ - 1 - t) * ELEMS + e;
            float x = X[ridx], g = G[ridx];
            float r = fmaf(g, h - x, x);
            h = tanhf(x * r);
            Yr[(size_t)t * ELEMS + e] = h;
        }
        dout[XXOFF + 1 * ELEMS + e] = h;
    }
}

// ---------------------------------------------------------------------------
// Layer-1 scan, writes final xx directly into d_out:
//   ltr: out[(b*SEQ + t)*2H + h]
//   rtl: out[(b*SEQ + (SEQ-1-t))*2H + H + h]
// h_last -> slots 2 (ltr) / 3 (rtl).
// ---------------------------------------------------------------------------
__global__ __launch_bounds__(256)
void scan_l1(const float* __restrict__ Xl, const float* __restrict__ Gl,
             const float* __restrict__ Xr, const float* __restrict__ Gr,
             float* __restrict__ dout)
{
    const int e   = (blockIdx.x & 31) * 256 + threadIdx.x;
    const int dir = blockIdx.x >> 5;
    const int b   = e >> 8;          // /HD
    const int hh  = e & (HD - 1);
    float h = 0.f;
    if (dir == 0) {
        #pragma unroll 2
        for (int t = 0; t < SEQ; t++) {
            size_t idx = (size_t)t * ELEMS + e;
            float x = Xl[idx], g = Gl[idx];
            float r = fmaf(g, h - x, x);
            h = tanhf(x * r);
            dout[((size_t)b * SEQ + t) * (2 * HD) + hh] = h;
        }
        dout[XXOFF + 2 * ELEMS + e] = h;
    } else {
        #pragma unroll 2
        for (int t = 0; t < SEQ; t++) {
            size_t idx = (size_t)t * ELEMS + e;
            float x = Xr[idx], g = Gr[idx];
            float r = fmaf(g, h - x, x);
            h = tanhf(x * r);
            dout[((size_t)b * SEQ + (SEQ - 1 - t)) * (2 * HD) + HD + hh] = h;
        }
        dout[XXOFF + 3 * ELEMS + e] = h;
    }
}

// ---------------------------------------------------------------------------
// Launch: proj GEMM -> gate0 GEMM -> scan0 -> gate1(l) -> gate1(r) -> scan1
// Inputs (metadata order): x, W_fc, b_fc, W1, b1, W2, b2.  W1/b1 unused
// (left blend is mathematically the identity).
// ---------------------------------------------------------------------------
extern "C" void kernel_launch(void* const* d_in, const int* in_sizes, int n_in,
                              void* d_out, int out_size)
{
    (void)in_sizes; (void)n_in; (void)out_size;
    const float* x    = (const float*)d_in[0];
    const float* W_fc = (const float*)d_in[1];
    const float* b_fc = (const float*)d_in[2];
    const float* W2   = (const float*)d_in[5];
    const float* b2   = (const float*)d_in[6];
    float* out = (float*)d_out;

    float *X0, *G0, *Y0l, *Y0r;
    { void* p; cudaGetSymbolAddress(&p, g_buf0); X0  = (float*)p; }
    { void* p; cudaGetSymbolAddress(&p, g_buf1); G0  = (float*)p; }
    { void* p; cudaGetSymbolAddress(&p, g_buf2); Y0l = (float*)p; }
    { void* p; cudaGetSymbolAddress(&p, g_buf3); Y0r = (float*)p; }
    float* G1l = X0;   // reuse after layer-0 scan consumed X0
    float* G1r = G0;   // reuse after layer-0 scan consumed G0

    dim3 ggrid(HD / BN, MROWS / BM);   // (2, 512)

    // 1) input projection -> X0 (scan order [t][b][h])
    gemm_fused<0><<<ggrid, 256>>>(x, W_fc, b_fc, X0, IND);
    // 2) layer-0 gates (shared by both directions)
    gemm_fused<1><<<ggrid, 256>>>(X0, W2 + 0 * HD * HD, b2 + 0 * HD, G0, HD);
    // 3) layer-0 scans (both directions)
    scan_l0<<<64, 256>>>(X0, G0, Y0l, Y0r, out);
    // 4) layer-1 gates, one GEMM per direction
    gemm_fused<1><<<ggrid, 256>>>(Y0l, W2 + 1 * HD * HD, b2 + 1 * HD, G1l, HD);
    gemm_fused<1><<<ggrid, 256>>>(Y0r, W2 + 1 * HD * HD, b2 + 1 * HD, G1r, HD);
    // 5) layer-1 scans write final outputs (xx + h_last slots 2,3)
    scan_l1<<<64, 256>>>(Y0l, G1l, Y0r, G1r, out);
}

// round 4
// speedup vs baseline: 1.7760x; 1.7760x over previous
#include <cuda_runtime.h>
#include <math.h>
#include <stdint.h>

// Problem constants
#define SEQ  2048
#define BSZ  32
#define HD   256
#define IND  512
#define MROWS (SEQ*BSZ)        // 65536
#define ELEMS (BSZ*HD)         // 8192 chains per direction
#define XXOFF ((size_t)BSZ*SEQ*2*HD)

// Scratch
__device__ float g_buf0[MROWS*HD];
__device__ float g_buf1[MROWS*HD];
__device__ float g_buf2[MROWS*HD];
__device__ float g_buf3[MROWS*HD];

// ---------------------------------------------------------------------------
// TF32 tensor-core GEMM: C[m,n] = act( sum_k A[m,k]*W[n,k] + bias[n] )
// BM=BN=128, BK=32, 256 threads = 8 warps (2 m x 4 n), each warp 64x32,
// per warp 4x4 tiles of m16n8k8. Register-double-buffered gmem loads,
// cvt.rna.tf32 applied at smem-store time.
// MODE 0: identity + scan-order row remap (m=b*SEQ+t -> t*BSZ+b)
// MODE 1: sigmoid, row = m
// ---------------------------------------------------------------------------
#define BM 128
#define BN 128
#define BK 32
#define PAD 4
#define BKW (BK+PAD)   // 36 words per row; 36*4=144 bytes, 16B-aligned

__device__ __forceinline__ uint32_t f2tf(float f) {
    uint32_t r;
    asm("cvt.rna.tf32.f32 %0, %1;" : "=r"(r) : "f"(f));
    return r;
}

__device__ __forceinline__ void mma_tf32(float* c, const uint32_t* a, const uint32_t* b) {
    asm("mma.sync.aligned.m16n8k8.row.col.f32.tf32.tf32.f32 "
        "{%0,%1,%2,%3},{%4,%5,%6,%7},{%8,%9},{%0,%1,%2,%3};"
        : "+f"(c[0]), "+f"(c[1]), "+f"(c[2]), "+f"(c[3])
        : "r"(a[0]), "r"(a[1]), "r"(a[2]), "r"(a[3]), "r"(b[0]), "r"(b[1]));
}

__device__ __forceinline__ float fast_rcp(float x) {
    float r;
    asm("rcp.approx.f32 %0, %1;" : "=f"(r) : "f"(x));
    return r;
}
__device__ __forceinline__ float fast_ex2(float x) {
    float r;
    asm("ex2.approx.f32 %0, %1;" : "=f"(r) : "f"(x));
    return r;
}

template<int MODE>
__global__ __launch_bounds__(256)
void gemm_tc(const float* __restrict__ A, const float* __restrict__ W,
             const float* __restrict__ bias, float* __restrict__ out, int K)
{
    __shared__ uint32_t As[BM * BKW];
    __shared__ uint32_t Ws[BN * BKW];

    const int tid  = threadIdx.x;
    const int m0   = blockIdx.y * BM;
    const int n0   = blockIdx.x * BN;
    const int warp = tid >> 5;
    const int lane = tid & 31;
    const int wm   = warp & 1;      // 0..1
    const int wn   = warp >> 1;     // 0..3
    const int lr   = lane >> 2;     // 0..7
    const int lc   = lane & 3;      // 0..3

    float acc[16][4];
    #pragma unroll
    for (int i = 0; i < 16; i++)
        #pragma unroll
        for (int j = 0; j < 4; j++) acc[i][j] = 0.f;

    // Global-load geometry: per pass p in 0..3, f = tid + 256p (0..1023)
    // row = f>>3 (0..127), c4 = (f&7)*4
    uint4 ra[4], rb[4];

    #define LOAD_TILES(k0)                                                        \
    {                                                                             \
        _Pragma("unroll")                                                         \
        for (int p = 0; p < 4; p++) {                                             \
            int f   = tid + p * 256;                                              \
            int row = f >> 3;                                                     \
            int c4  = (f & 7) * 4;                                                \
            float4 va = *(const float4*)(A + (size_t)(m0 + row) * K + (k0) + c4); \
            ra[p].x = f2tf(va.x); ra[p].y = f2tf(va.y);                           \
            ra[p].z = f2tf(va.z); ra[p].w = f2tf(va.w);                           \
            float4 vw = *(const float4*)(W + (size_t)(n0 + row) * K + (k0) + c4); \
            rb[p].x = f2tf(vw.x); rb[p].y = f2tf(vw.y);                           \
            rb[p].z = f2tf(vw.z); rb[p].w = f2tf(vw.w);                           \
        }                                                                         \
    }

    #define STORE_TILES()                                   \
    {                                                       \
        _Pragma("unroll")                                   \
        for (int p = 0; p < 4; p++) {                       \
            int f   = tid + p * 256;                        \
            int row = f >> 3;                               \
            int c4  = (f & 7) * 4;                          \
            *(uint4*)&As[row * BKW + c4] = ra[p];           \
            *(uint4*)&Ws[row * BKW + c4] = rb[p];           \
        }                                                   \
    }

    const int nk = K / BK;
    LOAD_TILES(0);
    STORE_TILES();
    __syncthreads();

    for (int kt = 0; kt < nk; kt++) {
        if (kt + 1 < nk) LOAD_TILES((kt + 1) * BK);

        // compute over smem tile: 4 k-steps of m16n8k8
        #pragma unroll
        for (int ks = 0; ks < 4; ks++) {
            const int kb = ks * 8;
            uint32_t af[4][4], bf[4][2];
            #pragma unroll
            for (int mt = 0; mt < 4; mt++) {
                int row = wm * 64 + mt * 16 + lr;
                af[mt][0] = As[row * BKW + kb + lc];
                af[mt][1] = As[(row + 8) * BKW + kb + lc];
                af[mt][2] = As[row * BKW + kb + lc + 4];
                af[mt][3] = As[(row + 8) * BKW + kb + lc + 4];
            }
            #pragma unroll
            for (int nt = 0; nt < 4; nt++) {
                int col = wn * 32 + nt * 8 + lr;
                bf[nt][0] = Ws[col * BKW + kb + lc];
                bf[nt][1] = Ws[col * BKW + kb + lc + 4];
            }
            #pragma unroll
            for (int mt = 0; mt < 4; mt++)
                #pragma unroll
                for (int nt = 0; nt < 4; nt++)
                    mma_tf32(acc[mt * 4 + nt], af[mt], bf[nt]);
        }

        __syncthreads();
        if (kt + 1 < nk) {
            STORE_TILES();
            __syncthreads();
        }
    }

    // Epilogue: per tile, 2 rows x (2 consecutive cols) -> float2 stores
    #pragma unroll
    for (int mt = 0; mt < 4; mt++) {
        #pragma unroll
        for (int rh = 0; rh < 2; rh++) {
            int m = m0 + wm * 64 + mt * 16 + lr + rh * 8;
            size_t orow;
            if (MODE == 0) {
                int b = m >> 11;              // /SEQ
                int t = m & (SEQ - 1);
                orow = (size_t)(t * BSZ + b) * HD;
            } else {
                orow = (size_t)m * HD;
            }
            #pragma unroll
            for (int nt = 0; nt < 4; nt++) {
                int n = n0 + wn * 32 + nt * 8 + 2 * lc;
                float v0 = acc[mt * 4 + nt][rh * 2 + 0] + bias[n];
                float v1 = acc[mt * 4 + nt][rh * 2 + 1] + bias[n + 1];
                if (MODE == 1) {
                    v0 = fast_rcp(1.0f + fast_ex2(-1.4426950408889634f * v0));
                    v1 = fast_rcp(1.0f + fast_ex2(-1.4426950408889634f * v1));
                }
                *(float2*)(out + orow + n) = make_float2(v0, v1);
            }
        }
    }
    #undef LOAD_TILES
    #undef STORE_TILES
}

// ---------------------------------------------------------------------------
// tanh(y) = 1 - 2/(1+e^{2y}) via MUFU ex2 + rcp (rel err ~2^-22)
// ---------------------------------------------------------------------------
__device__ __forceinline__ float fast_tanh(float y) {
    float e = fast_ex2(y * 2.8853900817779268f);   // 2*log2(e)
    float r = fast_rcp(e + 1.0f);
    return fmaf(-2.0f, r, 1.0f);
}

// Layer-0 scan: blocks [0,32) ltr, [32,64) rtl.
__global__ __launch_bounds__(256)
void scan_l0(const float* __restrict__ X, const float* __restrict__ G,
             float* __restrict__ Yl, float* __restrict__ Yr,
             float* __restrict__ dout)
{
    const int e   = (blockIdx.x & 31) * 256 + threadIdx.x;
    const int dir = blockIdx.x >> 5;
    float h = 0.f;
    if (dir == 0) {
        #pragma unroll 4
        for (int t = 0; t < SEQ; t++) {
            size_t idx = (size_t)t * ELEMS + e;
            float x = X[idx], g = G[idx];
            float r = fmaf(g, h - x, x);
            h = fast_tanh(x * r);
            Yl[idx] = h;
        }
        dout[XXOFF + 0 * ELEMS + e] = h;
    } else {
        #pragma unroll 4
        for (int t = 0; t < SEQ; t++) {
            size_t ridx = (size_t)(SEQ - 1 - t) * ELEMS + e;
            float x = X[ridx], g = G[ridx];
            float r = fmaf(g, h - x, x);
            h = fast_tanh(x * r);
            Yr[(size_t)t * ELEMS + e] = h;
        }
        dout[XXOFF + 1 * ELEMS + e] = h;
    }
}

// Layer-1 scan: writes final xx + h_last slots 2/3 directly into d_out.
__global__ __launch_bounds__(256)
void scan_l1(const float* __restrict__ Xl, const float* __restrict__ Gl,
             const float* __restrict__ Xr, const float* __restrict__ Gr,
             float* __restrict__ dout)
{
    const int e   = (blockIdx.x & 31) * 256 + threadIdx.x;
    const int dir = blockIdx.x >> 5;
    const int b   = e >> 8;
    const int hh  = e & (HD - 1);
    float h = 0.f;
    if (dir == 0) {
        #pragma unroll 4
        for (int t = 0; t < SEQ; t++) {
            size_t idx = (size_t)t * ELEMS + e;
            float x = Xl[idx], g = Gl[idx];
            float r = fmaf(g, h - x, x);
            h = fast_tanh(x * r);
            dout[((size_t)b * SEQ + t) * (2 * HD) + hh] = h;
        }
        dout[XXOFF + 2 * ELEMS + e] = h;
    } else {
        #pragma unroll 4
        for (int t = 0; t < SEQ; t++) {
            size_t idx = (size_t)t * ELEMS + e;
            float x = Xr[idx], g = Gr[idx];
            float r = fmaf(g, h - x, x);
            h = fast_tanh(x * r);
            dout[((size_t)b * SEQ + (SEQ - 1 - t)) * (2 * HD) + HD + hh] = h;
        }
        dout[XXOFF + 3 * ELEMS + e] = h;
    }
}

// ---------------------------------------------------------------------------
extern "C" void kernel_launch(void* const* d_in, const int* in_sizes, int n_in,
                              void* d_out, int out_size)
{
    (void)in_sizes; (void)n_in; (void)out_size;
    const float* x    = (const float*)d_in[0];
    const float* W_fc = (const float*)d_in[1];
    const float* b_fc = (const float*)d_in[2];
    const float* W2   = (const float*)d_in[5];
    const float* b2   = (const float*)d_in[6];
    float* out = (float*)d_out;

    float *X0, *G0, *Y0l, *Y0r;
    { void* p; cudaGetSymbolAddress(&p, g_buf0); X0  = (float*)p; }
    { void* p; cudaGetSymbolAddress(&p, g_buf1); G0  = (float*)p; }
    { void* p; cudaGetSymbolAddress(&p, g_buf2); Y0l = (float*)p; }
    { void* p; cudaGetSymbolAddress(&p, g_buf3); Y0r = (float*)p; }
    float* G1l = X0;   // reuse
    float* G1r = G0;   // reuse

    dim3 ggrid(HD / BN, MROWS / BM);   // (2, 512)

    gemm_tc<0><<<ggrid, 256>>>(x, W_fc, b_fc, X0, IND);
    gemm_tc<1><<<ggrid, 256>>>(X0, W2 + 0 * HD * HD, b2 + 0 * HD, G0, HD);
    scan_l0<<<64, 256>>>(X0, G0, Y0l, Y0r, out);
    gemm_tc<1><<<ggrid, 256>>>(Y0l, W2 + 1 * HD * HD, b2 + 1 * HD, G1l, HD);
    gemm_tc<1><<<ggrid, 256>>>(Y0r, W2 + 1 * HD * HD, b2 + 1 * HD, G1r, HD);
    scan_l1<<<64, 256>>>(Y0l, G1l, Y0r, G1r, out);
}

// round 7
// speedup vs baseline: 3.0957x; 1.7431x over previous
#include <cuda_runtime.h>
#include <math.h>
#include <stdint.h>

// Problem constants
#define SEQ  2048
#define BSZ  32
#define HD   256
#define IND  512
#define MROWS (SEQ*BSZ)        // 65536
#define ELEMS (BSZ*HD)         // 8192 chains per direction
#define XXOFF ((size_t)BSZ*SEQ*2*HD)

// Scratch
__device__ float g_buf0[MROWS*HD];
__device__ float g_buf1[MROWS*HD];
__device__ float g_buf2[MROWS*HD];
__device__ float g_buf3[MROWS*HD];

// ---------------------------------------------------------------------------
// helpers
// ---------------------------------------------------------------------------
__device__ __forceinline__ uint32_t f2tf(float f) {
    uint32_t r;
    asm("cvt.rna.tf32.f32 %0, %1;" : "=r"(r) : "f"(f));
    return r;
}
__device__ __forceinline__ void mma_tf32(float* c, const uint32_t* a, const uint32_t* b) {
    asm("mma.sync.aligned.m16n8k8.row.col.f32.tf32.tf32.f32 "
        "{%0,%1,%2,%3},{%4,%5,%6,%7},{%8,%9},{%0,%1,%2,%3};"
        : "+f"(c[0]), "+f"(c[1]), "+f"(c[2]), "+f"(c[3])
        : "r"(a[0]), "r"(a[1]), "r"(a[2]), "r"(a[3]), "r"(b[0]), "r"(b[1]));
}
__device__ __forceinline__ float fast_rcp(float x) {
    float r; asm("rcp.approx.f32 %0, %1;" : "=f"(r) : "f"(x)); return r;
}
__device__ __forceinline__ float fast_ex2(float x) {
    float r; asm("ex2.approx.f32 %0, %1;" : "=f"(r) : "f"(x)); return r;
}
__device__ __forceinline__ void cp16(uint32_t smem_addr, const float* gptr) {
    asm volatile("cp.async.cg.shared.global [%0], [%1], 16;" :: "r"(smem_addr), "l"(gptr));
}
#define CP_COMMIT() asm volatile("cp.async.commit_group;")
#define CP_WAIT1()  asm volatile("cp.async.wait_group 1;")

// ---------------------------------------------------------------------------
// TF32 TC GEMM with cp.async double buffering.
// C[m,n] = act( sum_k A[m,k]*W[n,k] + bias[n] )
// BM=BN=128, BK=32, 256 thr = 8 warps (2m x 4n), warp 64x32, 4x4 m16n8k8.
// fp32 in smem, cvt.rna.tf32 after LDS.
// MODE 0: identity + scan-order remap (m=b*SEQ+t -> t*BSZ+b); MODE 1: sigmoid.
// DUAL: blockIdx.y >= 512 switches to (A1, out1).
// ---------------------------------------------------------------------------
#define BM 128
#define BN 128
#define BK 32
#define BKW 36                       // 32 + 4 pad words
#define TILE_WORDS (128*BKW)         // per matrix per buffer
#define SMEM_BYTES (4*TILE_WORDS*4)  // 73728

template<int MODE, bool DUAL>
__global__ __launch_bounds__(256, 2)
void gemm_cp(const float* __restrict__ A0, const float* __restrict__ A1,
             const float* __restrict__ W, const float* __restrict__ bias,
             float* __restrict__ out0, float* __restrict__ out1, int K)
{
    extern __shared__ float sm[];
    // layout: [bufA0][bufA1][bufW0][bufW1]
    float* sA = sm;
    float* sW = sm + 2 * TILE_WORDS;

    const int tid  = threadIdx.x;
    int by = blockIdx.y;
    const float* A = A0;
    float* out = out0;
    if (DUAL && by >= 512) { A = A1; out = out1; by -= 512; }
    const int m0 = by * BM;
    const int n0 = blockIdx.x * BN;

    const int warp = tid >> 5;
    const int lane = tid & 31;
    const int wm   = warp & 1;
    const int wn   = warp >> 1;
    const int lr   = lane >> 2;
    const int lc   = lane & 3;

    float acc[16][4];
    #pragma unroll
    for (int i = 0; i < 16; i++)
        #pragma unroll
        for (int j = 0; j < 4; j++) acc[i][j] = 0.f;

    const uint32_t sA_base = (uint32_t)__cvta_generic_to_shared(sA);
    const uint32_t sW_base = (uint32_t)__cvta_generic_to_shared(sW);

    // issue cp.async for one BK tile into buffer `buf`
    #define ISSUE(k0, buf)                                                          \
    {                                                                               \
        _Pragma("unroll")                                                           \
        for (int p = 0; p < 4; p++) {                                               \
            int f   = tid + p * 256;                                                \
            int row = f >> 3;                                                       \
            int c4  = (f & 7) * 4;                                                  \
            uint32_t off = (uint32_t)((buf) * TILE_WORDS + row * BKW + c4) * 4u;    \
            cp16(sA_base + off, A + (size_t)(m0 + row) * K + (k0) + c4);            \
            cp16(sW_base + off, W + (size_t)(n0 + row) * K + (k0) + c4);            \
        }                                                                           \
    }

    const int nk = K / BK;
    ISSUE(0, 0);
    CP_COMMIT();

    for (int kt = 0; kt < nk; kt++) {
        if (kt + 1 < nk) ISSUE((kt + 1) * BK, (kt + 1) & 1);
        CP_COMMIT();
        CP_WAIT1();
        __syncthreads();

        const float* cA = sA + (kt & 1) * TILE_WORDS;
        const float* cW = sW + (kt & 1) * TILE_WORDS;

        #pragma unroll
        for (int ks = 0; ks < 4; ks++) {
            const int kb = ks * 8;
            uint32_t af[4][4], bf[4][2];
            #pragma unroll
            for (int mt = 0; mt < 4; mt++) {
                int row = wm * 64 + mt * 16 + lr;
                af[mt][0] = f2tf(cA[row * BKW + kb + lc]);
                af[mt][1] = f2tf(cA[(row + 8) * BKW + kb + lc]);
                af[mt][2] = f2tf(cA[row * BKW + kb + lc + 4]);
                af[mt][3] = f2tf(cA[(row + 8) * BKW + kb + lc + 4]);
            }
            #pragma unroll
            for (int nt = 0; nt < 4; nt++) {
                int col = wn * 32 + nt * 8 + lr;
                bf[nt][0] = f2tf(cW[col * BKW + kb + lc]);
                bf[nt][1] = f2tf(cW[col * BKW + kb + lc + 4]);
            }
            #pragma unroll
            for (int mt = 0; mt < 4; mt++)
                #pragma unroll
                for (int nt = 0; nt < 4; nt++)
                    mma_tf32(acc[mt * 4 + nt], af[mt], bf[nt]);
        }
        __syncthreads();
    }
    #undef ISSUE

    // Epilogue
    #pragma unroll
    for (int mt = 0; mt < 4; mt++) {
        #pragma unroll
        for (int rh = 0; rh < 2; rh++) {
            int m = m0 + wm * 64 + mt * 16 + lr + rh * 8;
            size_t orow;
            if (MODE == 0) {
                int b = m >> 11;              // /SEQ
                int t = m & (SEQ - 1);
                orow = (size_t)(t * BSZ + b) * HD;
            } else {
                orow = (size_t)m * HD;
            }
            #pragma unroll
            for (int nt = 0; nt < 4; nt++) {
                int n = n0 + wn * 32 + nt * 8 + 2 * lc;
                float v0 = acc[mt * 4 + nt][rh * 2 + 0] + bias[n];
                float v1 = acc[mt * 4 + nt][rh * 2 + 1] + bias[n + 1];
                if (MODE == 1) {
                    v0 = fast_rcp(1.0f + fast_ex2(-1.4426950408889634f * v0));
                    v1 = fast_rcp(1.0f + fast_ex2(-1.4426950408889634f * v1));
                }
                *(float2*)(out + orow + n) = make_float2(v0, v1);
            }
        }
    }
}

// ---------------------------------------------------------------------------
// Scans. 16-step chunked register prefetch; chain per step:
//   y2 = a*h + b;  e = ex2(y2);  r = rcp(e+1);  h = 1 - 2r
// with a = x*g*C, b = (x - x*g)*x*C off the critical path (C = 2*log2(e)).
// ---------------------------------------------------------------------------
#define CCONST 2.8853900817779268f
#define CH 16
#define NCH (SEQ/CH)   // 128

__device__ __forceinline__ void ld_chunk(const float* __restrict__ X,
                                         const float* __restrict__ G,
                                         size_t base, long long step,
                                         float (&x)[CH], float (&g)[CH])
{
    #pragma unroll
    for (int k = 0; k < CH; k++) {
        size_t idx = (size_t)((long long)base + (long long)k * step);
        x[k] = X[idx];
        g[k] = G[idx];
    }
}

__device__ __forceinline__ void proc_chunk(const float (&x)[CH], const float (&g)[CH],
                                           float& h, float* __restrict__ out,
                                           size_t obase, long long ostep)
{
    #pragma unroll
    for (int k = 0; k < CH; k++) {
        float t1 = x[k] * g[k];
        float a  = t1 * CCONST;
        float b  = (x[k] - t1) * x[k] * CCONST;
        float y2 = fmaf(a, h, b);
        float e  = fast_ex2(y2);
        float r  = fast_rcp(e + 1.0f);
        h = fmaf(-2.0f, r, 1.0f);
        out[(size_t)((long long)obase + (long long)k * ostep)] = h;
    }
}

// Layer-0: blocks [0,64) ltr, [64,128) rtl. X,G scan order [t][b][h].
__global__ __launch_bounds__(128)
void scan_l0(const float* __restrict__ X, const float* __restrict__ G,
             float* __restrict__ Yl, float* __restrict__ Yr,
             float* __restrict__ dout)
{
    const int e   = (blockIdx.x & 63) * 128 + threadIdx.x;   // 0..8191
    const int dir = blockIdx.x >> 6;
    float xA[CH], gA[CH], xB[CH], gB[CH];
    float h = 0.f;

    if (dir == 0) {
        const long long step = ELEMS;
        #define LB(c) ((size_t)(c) * CH * ELEMS + e)
        ld_chunk(X, G, LB(0), step, xA, gA);
        for (int c = 0; c < NCH; c += 2) {
            ld_chunk(X, G, LB(c + 1), step, xB, gB);
            proc_chunk(xA, gA, h, Yl, LB(c), step);
            if (c + 2 < NCH) ld_chunk(X, G, LB(c + 2), step, xA, gA);
            proc_chunk(xB, gB, h, Yl, LB(c + 1), step);
        }
        #undef LB
        dout[XXOFF + 0 * ELEMS + e] = h;
    } else {
        const long long lstep = -(long long)ELEMS;
        const long long ostep = ELEMS;
        #define LBR(c) ((size_t)(SEQ - 1 - (c) * CH) * ELEMS + e)
        #define OB(c)  ((size_t)(c) * CH * ELEMS + e)
        ld_chunk(X, G, LBR(0), lstep, xA, gA);
        for (int c = 0; c < NCH; c += 2) {
            ld_chunk(X, G, LBR(c + 1), lstep, xB, gB);
            proc_chunk(xA, gA, h, Yr, OB(c), ostep);
            if (c + 2 < NCH) ld_chunk(X, G, LBR(c + 2), lstep, xA, gA);
            proc_chunk(xB, gB, h, Yr, OB(c + 1), ostep);
        }
        #undef LBR
        #undef OB
        dout[XXOFF + 1 * ELEMS + e] = h;
    }
}

// Layer-1: writes final xx + h_last slots 2/3 directly to d_out.
__global__ __launch_bounds__(128)
void scan_l1(const float* __restrict__ Xl, const float* __restrict__ Gl,
             const float* __restrict__ Xr, const float* __restrict__ Gr,
             float* __restrict__ dout)
{
    const int e   = (blockIdx.x & 63) * 128 + threadIdx.x;
    const int dir = blockIdx.x >> 6;
    const int b   = e >> 8;
    const int hh  = e & (HD - 1);
    float xA[CH], gA[CH], xB[CH], gB[CH];
    float h = 0.f;

    if (dir == 0) {
        const long long lstep = ELEMS;
        const long long ostep = 2 * HD;
        #define LB(c) ((size_t)(c) * CH * ELEMS + e)
        #define OB(c) (((size_t)b * SEQ + (size_t)(c) * CH) * (2 * HD) + hh)
        ld_chunk(Xl, Gl, LB(0), lstep, xA, gA);
        for (int c = 0; c < NCH; c += 2) {
            ld_chunk(Xl, Gl, LB(c + 1), lstep, xB, gB);
            proc_chunk(xA, gA, h, dout, OB(c), ostep);
            if (c + 2 < NCH) ld_chunk(Xl, Gl, LB(c + 2), lstep, xA, gA);
            proc_chunk(xB, gB, h, dout, OB(c + 1), ostep);
        }
        #undef LB
        #undef OB
        dout[XXOFF + 2 * ELEMS + e] = h;
    } else {
        const long long lstep = ELEMS;
        const long long ostep = -(long long)(2 * HD);
        #define LB(c) ((size_t)(c) * CH * ELEMS + e)
        #define OB(c) (((size_t)b * SEQ + (size_t)(SEQ - 1 - (c) * CH)) * (2 * HD) + HD + hh)
        ld_chunk(Xr, Gr, LB(0), lstep, xA, gA);
        for (int c = 0; c < NCH; c += 2) {
            ld_chunk(Xr, Gr, LB(c + 1), lstep, xB, gB);
            proc_chunk(xA, gA, h, dout, OB(c), ostep);
            if (c + 2 < NCH) ld_chunk(Xr, Gr, LB(c + 2), lstep, xA, gA);
            proc_chunk(xB, gB, h, dout, OB(c + 1), ostep);
        }
        #undef LB
        #undef OB
        dout[XXOFF + 3 * ELEMS + e] = h;
    }
}

// ---------------------------------------------------------------------------
extern "C" void kernel_launch(void* const* d_in, const int* in_sizes, int n_in,
                              void* d_out, int out_size)
{
    (void)in_sizes; (void)n_in; (void)out_size;
    const float* x    = (const float*)d_in[0];
    const float* W_fc = (const float*)d_in[1];
    const float* b_fc = (const float*)d_in[2];
    const float* W2   = (const float*)d_in[5];
    const float* b2   = (const float*)d_in[6];
    float* out = (float*)d_out;

    float *X0, *G0, *Y0l, *Y0r;
    { void* p; cudaGetSymbolAddress(&p, g_buf0); X0  = (float*)p; }
    { void* p; cudaGetSymbolAddress(&p, g_buf1); G0  = (float*)p; }
    { void* p; cudaGetSymbolAddress(&p, g_buf2); Y0l = (float*)p; }
    { void* p; cudaGetSymbolAddress(&p, g_buf3); Y0r = (float*)p; }
    float* G1l = X0;   // reuse
    float* G1r = G0;   // reuse

    static bool attr_done = false;
    if (!attr_done) {
        cudaFuncSetAttribute(gemm_cp<0, false>, cudaFuncAttributeMaxDynamicSharedMemorySize, SMEM_BYTES);
        cudaFuncSetAttribute(gemm_cp<1, false>, cudaFuncAttributeMaxDynamicSharedMemorySize, SMEM_BYTES);
        cudaFuncSetAttribute(gemm_cp<1, true>,  cudaFuncAttributeMaxDynamicSharedMemorySize, SMEM_BYTES);
        attr_done = true;
    }

    dim3 g1(HD / BN, MROWS / BM);       // (2, 512)
    dim3 g2(HD / BN, 2 * (MROWS / BM)); // (2, 1024) dual

    // 1) input projection -> X0 (scan order)
    gemm_cp<0, false><<<g1, 256, SMEM_BYTES>>>(x, nullptr, W_fc, b_fc, X0, nullptr, IND);
    // 2) layer-0 gates (shared by both directions)
    gemm_cp<1, false><<<g1, 256, SMEM_BYTES>>>(X0, nullptr, W2, b2, G0, nullptr, HD);
    // 3) layer-0 scans
    scan_l0<<<128, 128>>>(X0, G0, Y0l, Y0r, out);
    // 4) layer-1 gates, both directions in one launch
    gemm_cp<1, true><<<g2, 256, SMEM_BYTES>>>(Y0l, Y0r, W2 + HD * HD, b2 + HD, G1l, G1r, HD);
    // 5) layer-1 scans -> final outputs
    scan_l1<<<128, 128>>>(Y0l, G1l, Y0r, G1r, out);
}

// round 8
// speedup vs baseline: 4.4790x; 1.4468x over previous
#include <cuda_runtime.h>
#include <math.h>
#include <stdint.h>

// Problem constants
#define SEQ  2048
#define BSZ  32
#define HD   256
#define IND  512
#define MROWS (SEQ*BSZ)        // 65536
#define ELEMS (BSZ*HD)         // 8192 chains per direction
#define XXOFF ((size_t)BSZ*SEQ*2*HD)

// Scratch
__device__ float g_buf0[MROWS*HD];
__device__ float g_buf1[MROWS*HD];
__device__ float g_buf2[MROWS*HD];
__device__ float g_buf3[MROWS*HD];

// ---------------------------------------------------------------------------
// helpers
// ---------------------------------------------------------------------------
__device__ __forceinline__ uint32_t f2tf(float f) {
    uint32_t r;
    asm("cvt.rna.tf32.f32 %0, %1;" : "=r"(r) : "f"(f));
    return r;
}
__device__ __forceinline__ void mma_tf32(float* c, const uint32_t* a, const uint32_t* b) {
    asm("mma.sync.aligned.m16n8k8.row.col.f32.tf32.tf32.f32 "
        "{%0,%1,%2,%3},{%4,%5,%6,%7},{%8,%9},{%0,%1,%2,%3};"
        : "+f"(c[0]), "+f"(c[1]), "+f"(c[2]), "+f"(c[3])
        : "r"(a[0]), "r"(a[1]), "r"(a[2]), "r"(a[3]), "r"(b[0]), "r"(b[1]));
}
__device__ __forceinline__ float fast_rcp(float x) {
    float r; asm("rcp.approx.f32 %0, %1;" : "=f"(r) : "f"(x)); return r;
}
__device__ __forceinline__ float fast_ex2(float x) {
    float r; asm("ex2.approx.f32 %0, %1;" : "=f"(r) : "f"(x)); return r;
}
__device__ __forceinline__ void cp16(uint32_t smem_addr, const float* gptr) {
    asm volatile("cp.async.cg.shared.global [%0], [%1], 16;" :: "r"(smem_addr), "l"(gptr));
}
#define CP_COMMIT() asm volatile("cp.async.commit_group;")
#define CP_WAIT1()  asm volatile("cp.async.wait_group 1;")
#define CP_WAIT2()  asm volatile("cp.async.wait_group 2;")

// ---------------------------------------------------------------------------
// TF32 TC GEMM with cp.async double buffering (unchanged from R7 — near the
// HMMA TF32 ceiling already).
// ---------------------------------------------------------------------------
#define BM 128
#define BN 128
#define BK 32
#define BKW 36
#define TILE_WORDS (128*BKW)
#define SMEM_BYTES (4*TILE_WORDS*4)  // 73728

template<int MODE, bool DUAL>
__global__ __launch_bounds__(256, 2)
void gemm_cp(const float* __restrict__ A0, const float* __restrict__ A1,
             const float* __restrict__ W, const float* __restrict__ bias,
             float* __restrict__ out0, float* __restrict__ out1, int K)
{
    extern __shared__ float sm[];
    float* sA = sm;
    float* sW = sm + 2 * TILE_WORDS;

    const int tid  = threadIdx.x;
    int by = blockIdx.y;
    const float* A = A0;
    float* out = out0;
    if (DUAL && by >= 512) { A = A1; out = out1; by -= 512; }
    const int m0 = by * BM;
    const int n0 = blockIdx.x * BN;

    const int warp = tid >> 5;
    const int lane = tid & 31;
    const int wm   = warp & 1;
    const int wn   = warp >> 1;
    const int lr   = lane >> 2;
    const int lc   = lane & 3;

    float acc[16][4];
    #pragma unroll
    for (int i = 0; i < 16; i++)
        #pragma unroll
        for (int j = 0; j < 4; j++) acc[i][j] = 0.f;

    const uint32_t sA_base = (uint32_t)__cvta_generic_to_shared(sA);
    const uint32_t sW_base = (uint32_t)__cvta_generic_to_shared(sW);

    #define ISSUE(k0, buf)                                                          \
    {                                                                               \
        _Pragma("unroll")                                                           \
        for (int p = 0; p < 4; p++) {                                               \
            int f   = tid + p * 256;                                                \
            int row = f >> 3;                                                       \
            int c4  = (f & 7) * 4;                                                  \
            uint32_t off = (uint32_t)((buf) * TILE_WORDS + row * BKW + c4) * 4u;    \
            cp16(sA_base + off, A + (size_t)(m0 + row) * K + (k0) + c4);            \
            cp16(sW_base + off, W + (size_t)(n0 + row) * K + (k0) + c4);            \
        }                                                                           \
    }

    const int nk = K / BK;
    ISSUE(0, 0);
    CP_COMMIT();

    for (int kt = 0; kt < nk; kt++) {
        if (kt + 1 < nk) ISSUE((kt + 1) * BK, (kt + 1) & 1);
        CP_COMMIT();
        CP_WAIT1();
        __syncthreads();

        const float* cA = sA + (kt & 1) * TILE_WORDS;
        const float* cW = sW + (kt & 1) * TILE_WORDS;

        #pragma unroll
        for (int ks = 0; ks < 4; ks++) {
            const int kb = ks * 8;
            uint32_t af[4][4], bf[4][2];
            #pragma unroll
            for (int mt = 0; mt < 4; mt++) {
                int row = wm * 64 + mt * 16 + lr;
                af[mt][0] = f2tf(cA[row * BKW + kb + lc]);
                af[mt][1] = f2tf(cA[(row + 8) * BKW + kb + lc]);
                af[mt][2] = f2tf(cA[row * BKW + kb + lc + 4]);
                af[mt][3] = f2tf(cA[(row + 8) * BKW + kb + lc + 4]);
            }
            #pragma unroll
            for (int nt = 0; nt < 4; nt++) {
                int col = wn * 32 + nt * 8 + lr;
                bf[nt][0] = f2tf(cW[col * BKW + kb + lc]);
                bf[nt][1] = f2tf(cW[col * BKW + kb + lc + 4]);
            }
            #pragma unroll
            for (int mt = 0; mt < 4; mt++)
                #pragma unroll
                for (int nt = 0; nt < 4; nt++)
                    mma_tf32(acc[mt * 4 + nt], af[mt], bf[nt]);
        }
        __syncthreads();
    }
    #undef ISSUE

    #pragma unroll
    for (int mt = 0; mt < 4; mt++) {
        #pragma unroll
        for (int rh = 0; rh < 2; rh++) {
            int m = m0 + wm * 64 + mt * 16 + lr + rh * 8;
            size_t orow;
            if (MODE == 0) {
                int b = m >> 11;
                int t = m & (SEQ - 1);
                orow = (size_t)(t * BSZ + b) * HD;
            } else {
                orow = (size_t)m * HD;
            }
            #pragma unroll
            for (int nt = 0; nt < 4; nt++) {
                int n = n0 + wn * 32 + nt * 8 + 2 * lc;
                float v0 = acc[mt * 4 + nt][rh * 2 + 0] + bias[n];
                float v1 = acc[mt * 4 + nt][rh * 2 + 1] + bias[n + 1];
                if (MODE == 1) {
                    v0 = fast_rcp(1.0f + fast_ex2(-1.4426950408889634f * v0));
                    v1 = fast_rcp(1.0f + fast_ex2(-1.4426950408889634f * v1));
                }
                *(float2*)(out + orow + n) = make_float2(v0, v1);
            }
        }
    }
}

// ---------------------------------------------------------------------------
// Scans: cp.async smem-staged, r-carried recurrence.
//   r_k = rcp(1 + ex2( fma(q_k, r_{k-1}, p_k) )),  h_k = fma(-2, r_k, 1)
//   with a = x*g*C, b = (x - x*g)*x*C, p = a+b, q = -2a   (C = 2*log2 e)
// Block = 128 threads (one chain each). Chunk = 16 timesteps.
// 4-stage smem ring, 16KB/stage, producer prefetch distance = 3 chunks.
// ---------------------------------------------------------------------------
#define CCONST 2.8853900817779268f
#define CH 16
#define NCH (SEQ/CH)                 // 128
#define CHUNK_FLOATS (2*CH*128)      // 4096 (x block then g block)
#define SCAN_SMEM (4*CHUNK_FLOATS*4) // 65536

__device__ __forceinline__ float scan_core(
    const float* __restrict__ Xb,   // base at (row 0, this block's e0)
    const float* __restrict__ Gb,
    long long dt,                    // gmem row stride (+/- ELEMS)
    float* __restrict__ outp,        // output base for this thread
    long long ostep,                 // output stride per timestep
    float* s, int tid)
{
    const uint32_t sbase = (uint32_t)__cvta_generic_to_shared(s);

    #define SC_ISSUE(c)                                                             \
    {                                                                               \
        _Pragma("unroll")                                                           \
        for (int p = 0; p < 8; p++) {                                               \
            int f   = tid + p * 128;            /* 0..1023 */                       \
            int arr = f >> 9;                   /* 0 = x, 1 = g */                  \
            int rk  = (f >> 5) & 15;            /* row within chunk */              \
            int wo  = (f & 31) * 4;             /* float offset in row */           \
            const float* gp = (arr ? Gb : Xb) + (long long)((c) * CH + rk) * dt + wo; \
            uint32_t sa = sbase + (uint32_t)((((c) & 3) * CHUNK_FLOATS)             \
                          + arr * (CH * 128) + rk * 128 + wo) * 4u;                 \
            cp16(sa, gp);                                                           \
        }                                                                           \
    }

    SC_ISSUE(0); CP_COMMIT();
    SC_ISSUE(1); CP_COMMIT();
    SC_ISSUE(2); CP_COMMIT();

    float r = 0.5f;                              // h0 = 0  ->  r = 0.5
    for (int c = 0; c < NCH; c++) {
        CP_WAIT2();
        __syncthreads();
        const float* sx = s + (c & 3) * CHUNK_FLOATS;
        const float* sg = sx + CH * 128;
        #pragma unroll
        for (int k = 0; k < CH; k++) {
            float x  = sx[k * 128 + tid];
            float g  = sg[k * 128 + tid];
            float t1 = x * g;
            float a  = t1 * CCONST;
            float b  = (x - t1) * x * CCONST;
            float p  = a + b;
            float q  = -2.0f * a;
            float y  = fmaf(q, r, p);            // chain: FFMA
            float e  = fast_ex2(y);              // chain: EX2
            r        = fast_rcp(e + 1.0f);       // chain: FADD + RCP
            float h  = fmaf(-2.0f, r, 1.0f);     // off-chain
            outp[(long long)(c * CH + k) * ostep] = h;
        }
        if (c + 3 < NCH) SC_ISSUE(c + 3);
        CP_COMMIT();                             // commit even if empty: keeps group count aligned
    }
    #undef SC_ISSUE
    return fmaf(-2.0f, r, 1.0f);
}

// Layer-0: blocks [0,64) ltr, [64,128) rtl. X,G scan order [t][b][h].
__global__ __launch_bounds__(128)
void scan_l0(const float* __restrict__ X, const float* __restrict__ G,
             float* __restrict__ Yl, float* __restrict__ Yr,
             float* __restrict__ dout)
{
    extern __shared__ float s[];
    const int tid = threadIdx.x;
    const int blk = blockIdx.x & 63;
    const int dir = blockIdx.x >> 6;
    const int e0  = blk * 128;
    const int e   = e0 + tid;

    const size_t rbase = dir ? (size_t)(SEQ - 1) * ELEMS : 0;
    const long long dt = dir ? -(long long)ELEMS : (long long)ELEMS;
    float* outp = (dir ? Yr : Yl) + e;

    float h = scan_core(X + rbase + e0, G + rbase + e0, dt, outp, ELEMS, s, tid);
    dout[XXOFF + (size_t)dir * ELEMS + e] = h;
}

// Layer-1: reads dir-specific buffers (already scan order), writes final xx
// + h_last slots 2/3 directly into d_out.
__global__ __launch_bounds__(128)
void scan_l1(const float* __restrict__ Xl, const float* __restrict__ Gl,
             const float* __restrict__ Xr, const float* __restrict__ Gr,
             float* __restrict__ dout)
{
    extern __shared__ float s[];
    const int tid = threadIdx.x;
    const int blk = blockIdx.x & 63;
    const int dir = blockIdx.x >> 6;
    const int e0  = blk * 128;
    const int e   = e0 + tid;
    const int b   = e >> 8;
    const int hh  = e & (HD - 1);

    const float* X = dir ? Xr : Xl;
    const float* G = dir ? Gr : Gl;
    float* outp = dout + (size_t)b * SEQ * (2 * HD) + hh
                + (dir ? ((size_t)(SEQ - 1) * (2 * HD) + HD) : 0);
    const long long ostep = dir ? -(long long)(2 * HD) : (long long)(2 * HD);

    float h = scan_core(X + e0, G + e0, (long long)ELEMS, outp, ostep, s, tid);
    dout[XXOFF + (size_t)(2 + dir) * ELEMS + e] = h;
}

// ---------------------------------------------------------------------------
extern "C" void kernel_launch(void* const* d_in, const int* in_sizes, int n_in,
                              void* d_out, int out_size)
{
    (void)in_sizes; (void)n_in; (void)out_size;
    const float* x    = (const float*)d_in[0];
    const float* W_fc = (const float*)d_in[1];
    const float* b_fc = (const float*)d_in[2];
    const float* W2   = (const float*)d_in[5];
    const float* b2   = (const float*)d_in[6];
    float* out = (float*)d_out;

    float *X0, *G0, *Y0l, *Y0r;
    { void* p; cudaGetSymbolAddress(&p, g_buf0); X0  = (float*)p; }
    { void* p; cudaGetSymbolAddress(&p, g_buf1); G0  = (float*)p; }
    { void* p; cudaGetSymbolAddress(&p, g_buf2); Y0l = (float*)p; }
    { void* p; cudaGetSymbolAddress(&p, g_buf3); Y0r = (float*)p; }
    float* G1l = X0;   // reuse
    float* G1r = G0;   // reuse

    static bool attr_done = false;
    if (!attr_done) {
        cudaFuncSetAttribute(gemm_cp<0, false>, cudaFuncAttributeMaxDynamicSharedMemorySize, SMEM_BYTES);
        cudaFuncSetAttribute(gemm_cp<1, false>, cudaFuncAttributeMaxDynamicSharedMemorySize, SMEM_BYTES);
        cudaFuncSetAttribute(gemm_cp<1, true>,  cudaFuncAttributeMaxDynamicSharedMemorySize, SMEM_BYTES);
        cudaFuncSetAttribute(scan_l0, cudaFuncAttributeMaxDynamicSharedMemorySize, SCAN_SMEM);
        cudaFuncSetAttribute(scan_l1, cudaFuncAttributeMaxDynamicSharedMemorySize, SCAN_SMEM);
        attr_done = true;
    }

    dim3 g1(HD / BN, MROWS / BM);       // (2, 512)
    dim3 g2(HD / BN, 2 * (MROWS / BM)); // (2, 1024) dual

    gemm_cp<0, false><<<g1, 256, SMEM_BYTES>>>(x, nullptr, W_fc, b_fc, X0, nullptr, IND);
    gemm_cp<1, false><<<g1, 256, SMEM_BYTES>>>(X0, nullptr, W2, b2, G0, nullptr, HD);
    scan_l0<<<128, 128, SCAN_SMEM>>>(X0, G0, Y0l, Y0r, out);
    gemm_cp<1, true><<<g2, 256, SMEM_BYTES>>>(Y0l, Y0r, W2 + HD * HD, b2 + HD, G1l, G1r, HD);
    scan_l1<<<128, 128, SCAN_SMEM>>>(Y0l, G1l, Y0r, G1r, out);
}

// round 14
// speedup vs baseline: 4.6658x; 1.0417x over previous
#include <cuda_runtime.h>
#include <math.h>
#include <stdint.h>

// Problem constants
#define SEQ  2048
#define BSZ  32
#define HD   256
#define IND  512
#define MROWS (SEQ*BSZ)        // 65536
#define ELEMS (BSZ*HD)         // 8192 chains per direction
#define XXOFF ((size_t)BSZ*SEQ*2*HD)

// Scratch (device globals; allocation is forbidden)
__device__ float g_buf0[MROWS*HD];   // X0 (f32, scan order); reused as G1l
__device__ float g_buf1[MROWS*HD];   // G0;                  reused as G1r
__device__ float g_buf2[MROWS*HD];   // Y0l (f32)
__device__ float g_buf3[MROWS*HD];   // Y0r (f32)
__device__ float g_buf4[MROWS*HD];   // X0tf (tf32-rounded)
__device__ float g_buf5[MROWS*HD];   // Y0l_tf
__device__ float g_buf6[MROWS*HD];   // Y0r_tf
__device__ float g_wts[262144];      // rounded weights: Wfc | W2_0 | W2_1

// ---------------------------------------------------------------------------
// helpers
// ---------------------------------------------------------------------------
__device__ __forceinline__ uint32_t f2tf(float f) {
    uint32_t r;
    asm("cvt.rna.tf32.f32 %0, %1;" : "=r"(r) : "f"(f));
    return r;
}
__device__ __forceinline__ void mma_tf32(float* c, const uint32_t* a, const uint32_t* b) {
    asm("mma.sync.aligned.m16n8k8.row.col.f32.tf32.tf32.f32 "
        "{%0,%1,%2,%3},{%4,%5,%6,%7},{%8,%9},{%0,%1,%2,%3};"
        : "+f"(c[0]), "+f"(c[1]), "+f"(c[2]), "+f"(c[3])
        : "r"(a[0]), "r"(a[1]), "r"(a[2]), "r"(a[3]), "r"(b[0]), "r"(b[1]));
}
__device__ __forceinline__ float fast_rcp(float x) {
    float r; asm("rcp.approx.f32 %0, %1;" : "=f"(r) : "f"(x)); return r;
}
__device__ __forceinline__ float fast_ex2(float x) {
    float r; asm("ex2.approx.f32 %0, %1;" : "=f"(r) : "f"(x)); return r;
}
__device__ __forceinline__ void cp16(uint32_t smem_addr, const float* gptr) {
    asm volatile("cp.async.cg.shared.global [%0], [%1], 16;" :: "r"(smem_addr), "l"(gptr));
}
#define CP_COMMIT() asm volatile("cp.async.commit_group;")
#define CP_WAITG1() asm volatile("cp.async.wait_group 1;")
#define CP_WAITG2() asm volatile("cp.async.wait_group 2;")

// ---------------------------------------------------------------------------
// Weight preround: g_wts = cvt.rna.tf32(Wfc | W2)  (one-time per launch, ~3us)
// ---------------------------------------------------------------------------
__global__ __launch_bounds__(128)
void preround_w(const float4* __restrict__ wfc, const float4* __restrict__ w2,
                float4* __restrict__ dst)
{
    int i = blockIdx.x * 128 + threadIdx.x;    // 0..65535
    float4 v = (i < 32768) ? wfc[i] : w2[i - 32768];
    float4 o;
    o.x = __uint_as_float(f2tf(v.x));
    o.y = __uint_as_float(f2tf(v.y));
    o.z = __uint_as_float(f2tf(v.z));
    o.w = __uint_as_float(f2tf(v.w));
    dst[i] = o;
}

// ---------------------------------------------------------------------------
// TF32 mma.sync GEMM, cvt-free inner loop.
// C[m,n] = act( sum_k A[m,k]*W[n,k] + bias[n] )
// BM=BN=128, BK=32. 128 threads = 4 warps (2m x 2n), warp tile 64x64,
// per warp 4x8 tiles of m16n8k8. 3-stage cp.async ring.
// Operands in smem are already tf32-rounded f32 bit patterns, except A when
// ACVT (proj, A = raw x): cvt at fragment load.
// MODE 0: identity + scan-order remap (m=b*SEQ+t -> t*BSZ+b) + rounded copy.
// MODE 1: sigmoid.  DUAL: blockIdx.y >= 512 -> (A1, out1).
// ---------------------------------------------------------------------------
#define BM 128
#define BN 128
#define BK 32
#define BKW 36                        // padded row: conflict-free LDS
#define STGW (128*BKW)                // words per matrix per stage (4608)
#define GSMEM (3*2*STGW*4)            // 110592 bytes

template<int MODE, bool ACVT, bool DUAL>
__global__ __launch_bounds__(128, 2)
void gemm_tc(const float* __restrict__ A0, const float* __restrict__ A1,
             const float* __restrict__ W, const float* __restrict__ bias,
             float* __restrict__ out0, float* __restrict__ out1,
             float* __restrict__ outtf, int K)
{
    extern __shared__ float sm[];

    const int tid  = threadIdx.x;          // 0..127
    const int warp = tid >> 5;
    const int lane = tid & 31;
    const int wm   = warp & 1;             // 0..1  (64-row half)
    const int wn   = warp >> 1;            // 0..1  (64-col half)
    const int lr   = lane >> 2;            // 0..7
    const int lc   = lane & 3;             // 0..3

    int by = blockIdx.y;
    const float* A = A0;
    float* out = out0;
    if (DUAL && by >= 512) { A = A1; out = out1; by -= 512; }
    const int m0 = by * BM;
    const int n0 = blockIdx.x * BN;

    float acc[32][4];                      // [mt*8+nt][4]
    #pragma unroll
    for (int i = 0; i < 32; i++)
        #pragma unroll
        for (int j = 0; j < 4; j++) acc[i][j] = 0.f;

    const uint32_t sbase = (uint32_t)__cvta_generic_to_shared(sm);

    // one BK tile: A 128x32 + W 128x32, 8 cp16 each per thread
    #define ISSUE(c)                                                               \
    {                                                                              \
        uint32_t so = (uint32_t)(((c) % 3) * 2 * STGW) * 4u;                       \
        _Pragma("unroll")                                                          \
        for (int p = 0; p < 8; p++) {                                              \
            int f   = tid + p * 128;             /* 0..1023 */                     \
            int row = f >> 3;                                                      \
            int c4  = (f & 7) * 4;                                                 \
            uint32_t off = (uint32_t)(row * BKW + c4) * 4u;                        \
            cp16(sbase + so + off, A + (size_t)(m0 + row) * K + (c) * BK + c4);    \
            cp16(sbase + so + (uint32_t)STGW * 4u + off,                           \
                 W + (size_t)(n0 + row) * K + (c) * BK + c4);                      \
        }                                                                          \
    }

    const int nk = K / BK;
    ISSUE(0); CP_COMMIT();
    ISSUE(1); CP_COMMIT();

    for (int kt = 0; kt < nk; kt++) {
        CP_WAITG1();                       // this thread's group kt complete
        __syncthreads();                   // all threads' copies visible; prev compute done
        if (kt + 2 < nk) ISSUE(kt + 2);
        CP_COMMIT();

        const float* cA = sm + (kt % 3) * 2 * STGW;
        const float* cW = cA + STGW;

        #pragma unroll
        for (int ks = 0; ks < 4; ks++) {
            const int kb = ks * 8;
            uint32_t af[4][4], bf[8][2];
            #pragma unroll
            for (int mt = 0; mt < 4; mt++) {
                int row = wm * 64 + mt * 16 + lr;
                if (ACVT) {
                    af[mt][0] = f2tf(cA[row * BKW + kb + lc]);
                    af[mt][1] = f2tf(cA[(row + 8) * BKW + kb + lc]);
                    af[mt][2] = f2tf(cA[row * BKW + kb + lc + 4]);
                    af[mt][3] = f2tf(cA[(row + 8) * BKW + kb + lc + 4]);
                } else {
                    af[mt][0] = __float_as_uint(cA[row * BKW + kb + lc]);
                    af[mt][1] = __float_as_uint(cA[(row + 8) * BKW + kb + lc]);
                    af[mt][2] = __float_as_uint(cA[row * BKW + kb + lc + 4]);
                    af[mt][3] = __float_as_uint(cA[(row + 8) * BKW + kb + lc + 4]);
                }
            }
            #pragma unroll
            for (int nt = 0; nt < 8; nt++) {
                int col = wn * 64 + nt * 8 + lr;
                bf[nt][0] = __float_as_uint(cW[col * BKW + kb + lc]);
                bf[nt][1] = __float_as_uint(cW[col * BKW + kb + lc + 4]);
            }
            #pragma unroll
            for (int mt = 0; mt < 4; mt++)
                #pragma unroll
                for (int nt = 0; nt < 8; nt++)
                    mma_tf32(acc[mt * 8 + nt], af[mt], bf[nt]);
        }
    }
    #undef ISSUE

    // Epilogue
    #pragma unroll
    for (int mt = 0; mt < 4; mt++) {
        #pragma unroll
        for (int rh = 0; rh < 2; rh++) {
            int m = m0 + wm * 64 + mt * 16 + lr + rh * 8;
            size_t orow;
            if (MODE == 0) {
                int b = m >> 11;               // /SEQ
                int t = m & (SEQ - 1);
                orow = (size_t)(t * BSZ + b) * HD;
            } else {
                orow = (size_t)m * HD;
            }
            #pragma unroll
            for (int nt = 0; nt < 8; nt++) {
                int n = n0 + wn * 64 + nt * 8 + 2 * lc;
                float v0 = acc[mt * 8 + nt][rh * 2 + 0] + bias[n];
                float v1 = acc[mt * 8 + nt][rh * 2 + 1] + bias[n + 1];
                if (MODE == 1) {
                    v0 = fast_rcp(1.0f + fast_ex2(-1.4426950408889634f * v0));
                    v1 = fast_rcp(1.0f + fast_ex2(-1.4426950408889634f * v1));
                }
                *(float2*)(out + orow + n) = make_float2(v0, v1);
                if (MODE == 0) {
                    float r0 = __uint_as_float(f2tf(v0));
                    float r1 = __uint_as_float(f2tf(v1));
                    *(float2*)(outtf + orow + n) = make_float2(r0, r1);
                }
            }
        }
    }
}

// ---------------------------------------------------------------------------
// Scans: cp.async smem-staged, r-carried recurrence.
//   r_k = rcp(1 + ex2( fma(q_k, r_{k-1}, p_k) )),  h_k = fma(-2, r_k, 1)
//   a = x*g*C, b = (x - x*g)*x*C, p = a+b, q = -2a   (C = 2*log2 e)
// WTF: also store tf32-rounded h (GEMM A-operand copy).
// ---------------------------------------------------------------------------
#define CCONST 2.8853900817779268f
#define CH 16
#define NCH (SEQ/CH)
#define CHUNK_FLOATS (2*CH*128)
#define SCAN_SMEM (4*CHUNK_FLOATS*4)

template<bool WTF>
__device__ __forceinline__ float scan_core(
    const float* __restrict__ Xb, const float* __restrict__ Gb,
    long long dt, float* __restrict__ outp, long long ostep,
    float* __restrict__ outtf, float* s, int tid)
{
    const uint32_t sbase = (uint32_t)__cvta_generic_to_shared(s);

    #define SC_ISSUE(c)                                                             \
    {                                                                               \
        _Pragma("unroll")                                                           \
        for (int p = 0; p < 8; p++) {                                               \
            int f   = tid + p * 128;                                                \
            int arr = f >> 9;                                                       \
            int rk  = (f >> 5) & 15;                                                \
            int wo  = (f & 31) * 4;                                                 \
            const float* gp = (arr ? Gb : Xb) + (long long)((c) * CH + rk) * dt + wo; \
            uint32_t sa = sbase + (uint32_t)((((c) & 3) * CHUNK_FLOATS)             \
                          + arr * (CH * 128) + rk * 128 + wo) * 4u;                 \
            cp16(sa, gp);                                                           \
        }                                                                           \
    }

    SC_ISSUE(0); CP_COMMIT();
    SC_ISSUE(1); CP_COMMIT();
    SC_ISSUE(2); CP_COMMIT();

    float r = 0.5f;
    for (int c = 0; c < NCH; c++) {
        CP_WAITG2();
        __syncthreads();
        const float* sx = s + (c & 3) * CHUNK_FLOATS;
        const float* sg = sx + CH * 128;
        #pragma unroll
        for (int k = 0; k < CH; k++) {
            float x  = sx[k * 128 + tid];
            float g  = sg[k * 128 + tid];
            float t1 = x * g;
            float a  = t1 * CCONST;
            float b  = (x - t1) * x * CCONST;
            float p  = a + b;
            float q  = -2.0f * a;
            float y  = fmaf(q, r, p);
            float e  = fast_ex2(y);
            r        = fast_rcp(e + 1.0f);
            float h  = fmaf(-2.0f, r, 1.0f);
            long long o = (long long)(c * CH + k) * ostep;
            outp[o] = h;
            if (WTF) outtf[o] = __uint_as_float(f2tf(h));
        }
        if (c + 3 < NCH) SC_ISSUE(c + 3);
        CP_COMMIT();
    }
    #undef SC_ISSUE
    return fmaf(-2.0f, r, 1.0f);
}

__global__ __launch_bounds__(128)
void scan_l0(const float* __restrict__ X, const float* __restrict__ G,
             float* __restrict__ Yl, float* __restrict__ Yr,
             float* __restrict__ Yltf, float* __restrict__ Yrtf,
             float* __restrict__ dout)
{
    extern __shared__ float s[];
    const int tid = threadIdx.x;
    const int blk = blockIdx.x & 63;
    const int dir = blockIdx.x >> 6;
    const int e0  = blk * 128;
    const int e   = e0 + tid;

    const size_t rbase = dir ? (size_t)(SEQ - 1) * ELEMS : 0;
    const long long dt = dir ? -(long long)ELEMS : (long long)ELEMS;
    float* outp   = (dir ? Yr : Yl) + e;
    float* outtfp = (dir ? Yrtf : Yltf) + e;

    float h = scan_core<true>(X + rbase + e0, G + rbase + e0, dt,
                              outp, ELEMS, outtfp, s, tid);
    dout[XXOFF + (size_t)dir * ELEMS + e] = h;
}

__global__ __launch_bounds__(128)
void scan_l1(const float* __restrict__ Xl, const float* __restrict__ Gl,
             const float* __restrict__ Xr, const float* __restrict__ Gr,
             float* __restrict__ dout)
{
    extern __shared__ float s[];
    const int tid = threadIdx.x;
    const int blk = blockIdx.x & 63;
    const int dir = blockIdx.x >> 6;
    const int e0  = blk * 128;
    const int e   = e0 + tid;
    const int b   = e >> 8;
    const int hh  = e & (HD - 1);

    const float* X = dir ? Xr : Xl;
    const float* G = dir ? Gr : Gl;
    float* outp = dout + (size_t)b * SEQ * (2 * HD) + hh
                + (dir ? ((size_t)(SEQ - 1) * (2 * HD) + HD) : 0);
    const long long ostep = dir ? -(long long)(2 * HD) : (long long)(2 * HD);

    float h = scan_core<false>(X + e0, G + e0, (long long)ELEMS,
                               outp, ostep, nullptr, s, tid);
    dout[XXOFF + (size_t)(2 + dir) * ELEMS + e] = h;
}

// ---------------------------------------------------------------------------
extern "C" void kernel_launch(void* const* d_in, const int* in_sizes, int n_in,
                              void* d_out, int out_size)
{
    (void)in_sizes; (void)n_in; (void)out_size;
    const float* x    = (const float*)d_in[0];
    const float* W_fc = (const float*)d_in[1];
    const float* b_fc = (const float*)d_in[2];
    const float* b2   = (const float*)d_in[6];
    float* out = (float*)d_out;

    float *X0, *G0, *Y0l, *Y0r, *X0tf, *Y0ltf, *Y0rtf, *wts;
    { void* p; cudaGetSymbolAddress(&p, g_buf0); X0    = (float*)p; }
    { void* p; cudaGetSymbolAddress(&p, g_buf1); G0    = (float*)p; }
    { void* p; cudaGetSymbolAddress(&p, g_buf2); Y0l   = (float*)p; }
    { void* p; cudaGetSymbolAddress(&p, g_buf3); Y0r   = (float*)p; }
    { void* p; cudaGetSymbolAddress(&p, g_buf4); X0tf  = (float*)p; }
    { void* p; cudaGetSymbolAddress(&p, g_buf5); Y0ltf = (float*)p; }
    { void* p; cudaGetSymbolAddress(&p, g_buf6); Y0rtf = (float*)p; }
    { void* p; cudaGetSymbolAddress(&p, g_wts);  wts   = (float*)p; }
    float* G1l = X0;   // X0 dead after scan0
    float* G1r = G0;   // G0 dead after scan0
    float* Wfc_tf = wts;
    float* W2_0tf = wts + 131072;
    float* W2_1tf = wts + 196608;

    static bool attr_done = false;
    if (!attr_done) {
        cudaFuncSetAttribute(gemm_tc<0, true,  false>, cudaFuncAttributeMaxDynamicSharedMemorySize, GSMEM);
        cudaFuncSetAttribute(gemm_tc<1, false, false>, cudaFuncAttributeMaxDynamicSharedMemorySize, GSMEM);
        cudaFuncSetAttribute(gemm_tc<1, false, true>,  cudaFuncAttributeMaxDynamicSharedMemorySize, GSMEM);
        cudaFuncSetAttribute(scan_l0, cudaFuncAttributeMaxDynamicSharedMemorySize, SCAN_SMEM);
        cudaFuncSetAttribute(scan_l1, cudaFuncAttributeMaxDynamicSharedMemorySize, SCAN_SMEM);
        attr_done = true;
    }

    dim3 g1(2, 512);
    dim3 g2(2, 1024);

    // 0) round weights to tf32 bit patterns
    preround_w<<<512, 128>>>((const float4*)W_fc, (const float4*)d_in[5], (float4*)wts);
    // 1) input projection -> X0 (f32, scan order) + X0tf (rounded)
    gemm_tc<0, true, false><<<g1, 128, GSMEM>>>(x, nullptr, Wfc_tf, b_fc, X0, nullptr, X0tf, IND);
    // 2) layer-0 gates (A = X0tf, no cvt in loop)
    gemm_tc<1, false, false><<<g1, 128, GSMEM>>>(X0tf, nullptr, W2_0tf, b2, G0, nullptr, nullptr, HD);
    // 3) layer-0 scans -> Y0 (f32) + Y0tf (rounded) + h_last slots 0/1
    scan_l0<<<128, 128, SCAN_SMEM>>>(X0, G0, Y0l, Y0r, Y0ltf, Y0rtf, out);
    // 4) layer-1 gates, both directions in one launch (A = Y0tf)
    gemm_tc<1, false, true><<<g2, 128, GSMEM>>>(Y0ltf, Y0rtf, W2_1tf, b2 + HD, G1l, G1r, nullptr, HD);
    // 5) layer-1 scans -> final xx + h_last slots 2/3
    scan_l1<<<128, 128, SCAN_SMEM>>>(Y0l, G1l, Y0r, G1r, out);
}

// round 15
// speedup vs baseline: 4.9971x; 1.0710x over previous
#include <cuda_runtime.h>
#include <cuda_fp16.h>
#include <math.h>
#include <stdint.h>

// Problem constants
#define SEQ  2048
#define BSZ  32
#define HD   256
#define IND  512
#define MROWS (SEQ*BSZ)        // 65536
#define ELEMS (BSZ*HD)         // 8192 chains per direction
#define XXOFF ((size_t)BSZ*SEQ*2*HD)

// Scratch (device globals)
__device__ float g_buf0[MROWS*HD];   // G1l
__device__ float g_buf1[MROWS*HD];   // G0, then G1r
__device__ float g_buf4[MROWS*HD];   // X0h (half, uses half the space)
__device__ float g_buf5[MROWS*HD];   // Y0lh (half)
__device__ float g_buf6[MROWS*HD];   // Y0rh (half)
__device__ float g_wts[131072];      // fp16 weights: Wfc | W2_0 | W2_1 (262144 halves)

// ---------------------------------------------------------------------------
// helpers
// ---------------------------------------------------------------------------
__device__ __forceinline__ float fast_rcp(float x) {
    float r; asm("rcp.approx.f32 %0, %1;" : "=f"(r) : "f"(x)); return r;
}
__device__ __forceinline__ float fast_ex2(float x) {
    float r; asm("ex2.approx.f32 %0, %1;" : "=f"(r) : "f"(x)); return r;
}
__device__ __forceinline__ void cp16(uint32_t smem_addr, const void* gptr) {
    asm volatile("cp.async.cg.shared.global [%0], [%1], 16;" :: "r"(smem_addr), "l"(gptr));
}
#define CP_COMMIT() asm volatile("cp.async.commit_group;")
#define CP_WAITG1() asm volatile("cp.async.wait_group 1;")
#define CP_WAITG2() asm volatile("cp.async.wait_group 2;")

__device__ __forceinline__ uint32_t pack2h(float lo, float hi) {
    __half2 h;
    h.x = __float2half_rn(lo);
    h.y = __float2half_rn(hi);
    return *reinterpret_cast<uint32_t*>(&h);
}
__device__ __forceinline__ void mma_f16(float* c, const uint32_t* a, const uint32_t* b) {
    asm("mma.sync.aligned.m16n8k16.row.col.f32.f16.f16.f32 "
        "{%0,%1,%2,%3},{%4,%5,%6,%7},{%8,%9},{%0,%1,%2,%3};"
        : "+f"(c[0]), "+f"(c[1]), "+f"(c[2]), "+f"(c[3])
        : "r"(a[0]), "r"(a[1]), "r"(a[2]), "r"(a[3]), "r"(b[0]), "r"(b[1]));
}

// ---------------------------------------------------------------------------
// Weight preround to fp16: dst = half(Wfc | W2)
// ---------------------------------------------------------------------------
__global__ __launch_bounds__(128)
void preround_h(const float4* __restrict__ wfc, const float4* __restrict__ w2,
                uint2* __restrict__ dst)
{
    int i = blockIdx.x * 128 + threadIdx.x;    // 0..65535 float4s
    float4 v = (i < 32768) ? wfc[i] : w2[i - 32768];
    uint2 o;
    o.x = pack2h(v.x, v.y);
    o.y = pack2h(v.z, v.w);
    dst[i] = o;
}

// ---------------------------------------------------------------------------
// fp16 mma.sync GEMM: C[m,n] = act( sum_k A[m,k]*W[n,k] + bias[n] )
// BM=BN=128, BK=32, 128 threads = 4 warps (2m x 2n), warp 64x64,
// per warp 4x8 tiles of m16n8k16 (2 k-steps per BK). 3-stage cp.async ring.
// W always fp16 in smem. A fp16 in smem, except ACVT (proj: A = raw f32 x,
// packed to half2 at fragment load).
// MODE 0: scan-order remap (m=b*SEQ+t -> t*BSZ+b), writes ONLY fp16 out.
// MODE 1: sigmoid, writes f32 out.  DUAL: blockIdx.y >= 512 -> (A1, out1).
// ---------------------------------------------------------------------------
#define BM 128
#define BN 128
#define BK 32

template<int MODE, bool ACVT, bool DUAL>
__global__ __launch_bounds__(128, 2)
void gemm_h(const void* __restrict__ A0v, const void* __restrict__ A1v,
            const __half* __restrict__ W, const float* __restrict__ bias,
            float* __restrict__ outf0, float* __restrict__ outf1,
            __half* __restrict__ outh, int K)
{
    constexpr int A_BYTES = ACVT ? (128 * 144) : (128 * 80);  // f32 row 36w pad / f16 row 40h pad
    constexpr int W_BYTES = 128 * 80;
    constexpr int STAGE   = A_BYTES + W_BYTES;

    extern __shared__ char sm[];

    const int tid  = threadIdx.x;
    const int warp = tid >> 5;
    const int lane = tid & 31;
    const int wm   = warp & 1;
    const int wn   = warp >> 1;
    const int lr   = lane >> 2;
    const int lc   = lane & 3;

    int by = blockIdx.y;
    const void* Av = A0v;
    float* outf = outf0;
    if (DUAL && by >= 512) { Av = A1v; outf = outf1; by -= 512; }
    const int m0 = by * BM;
    const int n0 = blockIdx.x * BN;

    float acc[32][4];
    #pragma unroll
    for (int i = 0; i < 32; i++)
        #pragma unroll
        for (int j = 0; j < 4; j++) acc[i][j] = 0.f;

    const uint32_t sbase = (uint32_t)__cvta_generic_to_shared(sm);

    #define ISSUE(c)                                                                \
    {                                                                               \
        uint32_t so = sbase + (uint32_t)(((c) % 3) * STAGE);                        \
        if (ACVT) {                                                                 \
            const float* Af = (const float*)Av;                                     \
            _Pragma("unroll")                                                       \
            for (int p = 0; p < 8; p++) {                                           \
                int f = tid + p * 128; int row = f >> 3; int cc = f & 7;            \
                cp16(so + (uint32_t)(row * 144 + cc * 16),                          \
                     (const void*)(Af + (size_t)(m0 + row) * K + (c) * BK + cc * 4)); \
            }                                                                       \
        } else {                                                                    \
            const __half* Ah = (const __half*)Av;                                   \
            _Pragma("unroll")                                                       \
            for (int p = 0; p < 4; p++) {                                           \
                int f = tid + p * 128; int row = f >> 2; int cc = f & 3;            \
                cp16(so + (uint32_t)(row * 80 + cc * 16),                           \
                     (const void*)(Ah + (size_t)(m0 + row) * K + (c) * BK + cc * 8)); \
            }                                                                       \
        }                                                                           \
        _Pragma("unroll")                                                           \
        for (int p = 0; p < 4; p++) {                                               \
            int f = tid + p * 128; int row = f >> 2; int cc = f & 3;                \
            cp16(so + (uint32_t)(A_BYTES + row * 80 + cc * 16),                     \
                 (const void*)(W + (size_t)(n0 + row) * K + (c) * BK + cc * 8));    \
        }                                                                           \
    }

    const int nk = K / BK;
    ISSUE(0); CP_COMMIT();
    ISSUE(1); CP_COMMIT();

    for (int kt = 0; kt < nk; kt++) {
        CP_WAITG1();
        __syncthreads();
        if (kt + 2 < nk) ISSUE(kt + 2);
        CP_COMMIT();

        const char* stg = sm + (kt % 3) * STAGE;
        const float*    cAf  = (const float*)stg;
        const uint32_t* cA32 = (const uint32_t*)stg;
        const uint32_t* cW32 = (const uint32_t*)(stg + A_BYTES);

        #pragma unroll
        for (int ks = 0; ks < 2; ks++) {
            uint32_t af[4][4], bf[8][2];
            #pragma unroll
            for (int mt = 0; mt < 4; mt++) {
                int row = wm * 64 + mt * 16 + lr;
                if (ACVT) {
                    float2 v0 = *(const float2*)&cAf[row * 36 + ks * 16 + 2 * lc];
                    float2 v1 = *(const float2*)&cAf[(row + 8) * 36 + ks * 16 + 2 * lc];
                    float2 v2 = *(const float2*)&cAf[row * 36 + ks * 16 + 2 * lc + 8];
                    float2 v3 = *(const float2*)&cAf[(row + 8) * 36 + ks * 16 + 2 * lc + 8];
                    af[mt][0] = pack2h(v0.x, v0.y);
                    af[mt][1] = pack2h(v1.x, v1.y);
                    af[mt][2] = pack2h(v2.x, v2.y);
                    af[mt][3] = pack2h(v3.x, v3.y);
                } else {
                    int idx = row * 20 + ks * 8 + lc;
                    af[mt][0] = cA32[idx];
                    af[mt][1] = cA32[idx + 160];      // +8 rows * 20 words
                    af[mt][2] = cA32[idx + 4];
                    af[mt][3] = cA32[idx + 164];
                }
            }
            #pragma unroll
            for (int nt = 0; nt < 8; nt++) {
                int col = wn * 64 + nt * 8 + lr;
                int idx = col * 20 + ks * 8 + lc;
                bf[nt][0] = cW32[idx];
                bf[nt][1] = cW32[idx + 4];
            }
            #pragma unroll
            for (int mt = 0; mt < 4; mt++)
                #pragma unroll
                for (int nt = 0; nt < 8; nt++)
                    mma_f16(acc[mt * 8 + nt], af[mt], bf[nt]);
        }
    }
    #undef ISSUE

    // Epilogue
    #pragma unroll
    for (int mt = 0; mt < 4; mt++) {
        #pragma unroll
        for (int rh = 0; rh < 2; rh++) {
            int m = m0 + wm * 64 + mt * 16 + lr + rh * 8;
            size_t orow;
            if (MODE == 0) {
                int b = m >> 11;               // /SEQ
                int t = m & (SEQ - 1);
                orow = (size_t)(t * BSZ + b) * HD;
            } else {
                orow = (size_t)m * HD;
            }
            #pragma unroll
            for (int nt = 0; nt < 8; nt++) {
                int n = n0 + wn * 64 + nt * 8 + 2 * lc;
                float v0 = acc[mt * 8 + nt][rh * 2 + 0] + bias[n];
                float v1 = acc[mt * 8 + nt][rh * 2 + 1] + bias[n + 1];
                if (MODE == 0) {
                    *(uint32_t*)(outh + orow + n) = pack2h(v0, v1);
                } else {
                    v0 = fast_rcp(1.0f + fast_ex2(-1.4426950408889634f * v0));
                    v1 = fast_rcp(1.0f + fast_ex2(-1.4426950408889634f * v1));
                    *(float2*)(outf + orow + n) = make_float2(v0, v1);
                }
            }
        }
    }
}

#define GSMEM_ACVT (3*(128*144 + 128*80))   // 86016
#define GSMEM_H    (3*(128*80 + 128*80))    // 61440

// ---------------------------------------------------------------------------
// Fused bidirectional scans. 128 blocks x 64 threads; each thread carries the
// ltr AND rtl chain for one element e = blk*64 + tid. Chunk = 8 steps,
// 4-stage cp.async ring, stage = xf(1K half) | xr(1K) | gf(2K f32) | gr(2K).
// Chain: r = rcp(1 + ex2(fma(-2a, r, a+b))); a = x*g*C, b = (x-xg)*x*C.
// ---------------------------------------------------------------------------
#define CCONST 2.8853900817779268f
#define SC_SMEM (4*6144)

// Layer 0: ltr reads rows ascending, rtl descending. Outputs fp16 Y + hlast.
__global__ __launch_bounds__(64)
void scan0_k(const __half* __restrict__ Xh, const float* __restrict__ G,
             __half* __restrict__ Ylh, __half* __restrict__ Yrh,
             float* __restrict__ dout)
{
    extern __shared__ char s[];
    const int tid = threadIdx.x;
    const int e0  = blockIdx.x * 64;
    const int e   = e0 + tid;
    const uint32_t sb = (uint32_t)__cvta_generic_to_shared(s);

    #define S0_ISSUE(c)                                                              \
    {                                                                                \
        int s0 = (c) * 8;                                                            \
        uint32_t st = sb + (uint32_t)(((c) & 3) * 6144);                             \
        { int row = tid >> 3, cc = tid & 7;                                          \
          cp16(st + (uint32_t)(row * 128 + cc * 16),                                 \
               (const void*)(Xh + (size_t)(s0 + row) * ELEMS + e0 + cc * 8));        \
          cp16(st + (uint32_t)(1024 + row * 128 + cc * 16),                          \
               (const void*)(Xh + (size_t)(2047 - (s0 + row)) * ELEMS + e0 + cc * 8)); } \
        _Pragma("unroll")                                                            \
        for (int p = 0; p < 2; p++) {                                                \
            int f = tid + p * 64; int row = f >> 4, cc = f & 15;                     \
            cp16(st + (uint32_t)(2048 + row * 256 + cc * 16),                        \
                 (const void*)(G + (size_t)(s0 + row) * ELEMS + e0 + cc * 4));       \
            cp16(st + (uint32_t)(4096 + row * 256 + cc * 16),                        \
                 (const void*)(G + (size_t)(2047 - (s0 + row)) * ELEMS + e0 + cc * 4)); } \
    }

    S0_ISSUE(0); CP_COMMIT();
    S0_ISSUE(1); CP_COMMIT();
    S0_ISSUE(2); CP_COMMIT();

    float rf = 0.5f, rr = 0.5f;
    for (int c = 0; c < 256; c++) {
        CP_WAITG2();
        __syncthreads();
        const char* st = s + (c & 3) * 6144;
        const __half* xf = (const __half*)st;
        const __half* xr = (const __half*)(st + 1024);
        const float*  gf = (const float*)(st + 2048);
        const float*  gr = (const float*)(st + 4096);
        #pragma unroll
        for (int k = 0; k < 8; k++) {
            int t = c * 8 + k;
            {
                float x = __half2float(xf[k * 64 + tid]);
                float g = gf[k * 64 + tid];
                float t1 = x * g, a = t1 * CCONST, b = (x - t1) * x * CCONST;
                float y = fmaf(-2.0f * a, rf, a + b);
                rf = fast_rcp(fast_ex2(y) + 1.0f);
                Ylh[(size_t)t * ELEMS + e] = __float2half_rn(fmaf(-2.0f, rf, 1.0f));
            }
            {
                float x = __half2float(xr[k * 64 + tid]);
                float g = gr[k * 64 + tid];
                float t1 = x * g, a = t1 * CCONST, b = (x - t1) * x * CCONST;
                float y = fmaf(-2.0f * a, rr, a + b);
                rr = fast_rcp(fast_ex2(y) + 1.0f);
                Yrh[(size_t)t * ELEMS + e] = __float2half_rn(fmaf(-2.0f, rr, 1.0f));
            }
        }
        if (c + 3 < 256) S0_ISSUE(c + 3);
        CP_COMMIT();
    }
    #undef S0_ISSUE
    dout[XXOFF + e]          = fmaf(-2.0f, rf, 1.0f);
    dout[XXOFF + ELEMS + e]  = fmaf(-2.0f, rr, 1.0f);
}

// Layer 1: both streams ascending (Y0r already in scan order). Writes final
// xx (f32) + hlast slots 2/3.
__global__ __launch_bounds__(64)
void scan1_k(const __half* __restrict__ Ylh, const float* __restrict__ Gl,
             const __half* __restrict__ Yrh, const float* __restrict__ Gr,
             float* __restrict__ dout)
{
    extern __shared__ char s[];
    const int tid = threadIdx.x;
    const int e0  = blockIdx.x * 64;
    const int e   = e0 + tid;
    const int b   = e >> 8;
    const int hh  = e & (HD - 1);
    const uint32_t sb = (uint32_t)__cvta_generic_to_shared(s);

    #define S1_ISSUE(c)                                                              \
    {                                                                                \
        int s0 = (c) * 8;                                                            \
        uint32_t st = sb + (uint32_t)(((c) & 3) * 6144);                             \
        { int row = tid >> 3, cc = tid & 7;                                          \
          cp16(st + (uint32_t)(row * 128 + cc * 16),                                 \
               (const void*)(Ylh + (size_t)(s0 + row) * ELEMS + e0 + cc * 8));       \
          cp16(st + (uint32_t)(1024 + row * 128 + cc * 16),                          \
               (const void*)(Yrh + (size_t)(s0 + row) * ELEMS + e0 + cc * 8)); }     \
        _Pragma("unroll")                                                            \
        for (int p = 0; p < 2; p++) {                                                \
            int f = tid + p * 64; int row = f >> 4, cc = f & 15;                     \
            cp16(st + (uint32_t)(2048 + row * 256 + cc * 16),                        \
                 (const void*)(Gl + (size_t)(s0 + row) * ELEMS + e0 + cc * 4));      \
            cp16(st + (uint32_t)(4096 + row * 256 + cc * 16),                        \
                 (const void*)(Gr + (size_t)(s0 + row) * ELEMS + e0 + cc * 4)); }    \
    }

    S1_ISSUE(0); CP_COMMIT();
    S1_ISSUE(1); CP_COMMIT();
    S1_ISSUE(2); CP_COMMIT();

    float* obase = dout + (size_t)b * SEQ * (2 * HD) + hh;
    float rf = 0.5f, rr = 0.5f;
    for (int c = 0; c < 256; c++) {
        CP_WAITG2();
        __syncthreads();
        const char* st = s + (c & 3) * 6144;
        const __half* xf = (const __half*)st;
        const __half* xr = (const __half*)(st + 1024);
        const float*  gf = (const float*)(st + 2048);
        const float*  gr = (const float*)(st + 4096);
        #pragma unroll
        for (int k = 0; k < 8; k++) {
            int t = c * 8 + k;
            {
                float x = __half2float(xf[k * 64 + tid]);
                float g = gf[k * 64 + tid];
                float t1 = x * g, a = t1 * CCONST, b2 = (x - t1) * x * CCONST;
                float y = fmaf(-2.0f * a, rf, a + b2);
                rf = fast_rcp(fast_ex2(y) + 1.0f);
                obase[(size_t)t * (2 * HD)] = fmaf(-2.0f, rf, 1.0f);
            }
            {
                float x = __half2float(xr[k * 64 + tid]);
                float g = gr[k * 64 + tid];
                float t1 = x * g, a = t1 * CCONST, b2 = (x - t1) * x * CCONST;
                float y = fmaf(-2.0f * a, rr, a + b2);
                rr = fast_rcp(fast_ex2(y) + 1.0f);
                obase[(size_t)(2047 - t) * (2 * HD) + HD] = fmaf(-2.0f, rr, 1.0f);
            }
        }
        if (c + 3 < 256) S1_ISSUE(c + 3);
        CP_COMMIT();
    }
    #undef S1_ISSUE
    dout[XXOFF + 2 * ELEMS + e] = fmaf(-2.0f, rf, 1.0f);
    dout[XXOFF + 3 * ELEMS + e] = fmaf(-2.0f, rr, 1.0f);
}

// ---------------------------------------------------------------------------
extern "C" void kernel_launch(void* const* d_in, const int* in_sizes, int n_in,
                              void* d_out, int out_size)
{
    (void)in_sizes; (void)n_in; (void)out_size;
    const float* x    = (const float*)d_in[0];
    const float* W_fc = (const float*)d_in[1];
    const float* b_fc = (const float*)d_in[2];
    const float* b2   = (const float*)d_in[6];
    float* out = (float*)d_out;

    float *G1l, *G0, *wraw;
    __half *X0h, *Ylh, *Yrh;
    { void* p; cudaGetSymbolAddress(&p, g_buf0); G1l = (float*)p; }
    { void* p; cudaGetSymbolAddress(&p, g_buf1); G0  = (float*)p; }
    { void* p; cudaGetSymbolAddress(&p, g_buf4); X0h = (__half*)p; }
    { void* p; cudaGetSymbolAddress(&p, g_buf5); Ylh = (__half*)p; }
    { void* p; cudaGetSymbolAddress(&p, g_buf6); Yrh = (__half*)p; }
    { void* p; cudaGetSymbolAddress(&p, g_wts);  wraw = (float*)p; }
    float* G1r = G0;                         // G0 dead after scan0
    __half* Wh    = (__half*)wraw;
    __half* W2_0h = Wh + 131072;
    __half* W2_1h = Wh + 196608;

    static bool attr_done = false;
    if (!attr_done) {
        cudaFuncSetAttribute(gemm_h<0, true,  false>, cudaFuncAttributeMaxDynamicSharedMemorySize, GSMEM_ACVT);
        cudaFuncSetAttribute(gemm_h<1, false, false>, cudaFuncAttributeMaxDynamicSharedMemorySize, GSMEM_H);
        cudaFuncSetAttribute(gemm_h<1, false, true>,  cudaFuncAttributeMaxDynamicSharedMemorySize, GSMEM_H);
        attr_done = true;
    }

    dim3 g1(2, 512);
    dim3 g2(2, 1024);

    // 0) weights -> fp16
    preround_h<<<512, 128>>>((const float4*)W_fc, (const float4*)d_in[5], (uint2*)Wh);
    // 1) input projection -> X0h (fp16, scan order)
    gemm_h<0, true, false><<<g1, 128, GSMEM_ACVT>>>(x, nullptr, Wh, b_fc, nullptr, nullptr, X0h, IND);
    // 2) layer-0 gates (f32)
    gemm_h<1, false, false><<<g1, 128, GSMEM_H>>>(X0h, nullptr, W2_0h, b2, G0, nullptr, nullptr, HD);
    // 3) layer-0 fused bidirectional scan -> Ylh/Yrh (fp16) + hlast 0/1
    scan0_k<<<128, 64, SC_SMEM>>>(X0h, G0, Ylh, Yrh, out);
    // 4) layer-1 gates, both directions in one launch
    gemm_h<1, false, true><<<g2, 128, GSMEM_H>>>(Ylh, Yrh, W2_1h, b2 + HD, G1l, G1r, nullptr, HD);
    // 5) layer-1 fused scan -> final xx + hlast 2/3
    scan1_k<<<128, 64, SC_SMEM>>>(Ylh, G1l, Yrh, G1r, out);
}